// round 2
// baseline (speedup 1.0000x reference)
#include <cuda_runtime.h>

#define H 256
#define DD 64
#define NDIR 6112
#define GDIR 16
#define NBLK (NDIR / GDIR)   // 382
#define KT 32                // K-tile (m per stage)
#define SW_STRIDE 260        // padded smem stride for W2T tile (16B-aligned rows, low conflicts)

// ---------------- persistent device state (no allocations) ----------------
__device__ double g_accum = 0.0;
__device__ unsigned int g_done = 0;

// ---------------- f32x2 packed-FMA helpers (Blackwell) ----------------
__device__ __forceinline__ unsigned long long pk2(float a, float b) {
    unsigned long long r;
    asm("mov.b64 %0, {%1, %2};" : "=l"(r) : "f"(a), "f"(b));
    return r;
}
__device__ __forceinline__ unsigned long long f2(unsigned long long a,
                                                 unsigned long long b,
                                                 unsigned long long c) {
    unsigned long long d;
    asm("fma.rn.f32x2 %0, %1, %2, %3;" : "=l"(d) : "l"(a), "l"(b), "l"(c));
    return d;
}
__device__ __forceinline__ void up2(unsigned long long v, float& a, float& b) {
    asm("mov.b64 {%0, %1}, %2;" : "=f"(a), "=f"(b) : "l"(v));
}

// ---------------- single fused kernel ----------------
// Per block (16 directions):
//   phase 0: decode dirs; layer-1 forward (h0, jet constants c1..c4); build jet
//            columns sH[256 m][64 cols] where col = dirLocal*4 + (k-1),
//            h_k[m] = c_k[m] * u1[m]^k with u1 = cA*W1[:,i] + cB*W1[:,j].
//   phase 1: K-tiled GEMM a_k[n] = sum_m W2[n,m] h_k[m]; W2T staged per 32-m
//            tile in smem from coalesced W2 row reads; f32x2 packed FMAs;
//            a0[n] = sum_m W2[n,m] h0[m] folded into the same loop.
//   phase 2: layer-2 order-4 tanh jet recurrence; w3 . g4; polarization weight;
//            block reduce; one double atomic; last block writes out + resets.
__global__ __launch_bounds__(256, 2) void k_all(
    const float* __restrict__ x,  const float* __restrict__ W1,
    const float* __restrict__ b1, const float* __restrict__ W2,
    const float* __restrict__ b2, const float* __restrict__ W3,
    float* __restrict__ out)
{
    extern __shared__ float sm[];
    float* sH  = sm;                      // 16384 floats: jets [m][64]
    float* sW  = sm + 16384;              // 8320 floats: W2T tile [32][260]
    float* sh0 = sm + 16384 + 8320;       // 256 floats: h0
    float* sx  = sh0 + H;                 // 64 floats: x
    __shared__ int   sI[GDIR], sJ[GDIR];
    __shared__ float sCA[GDIR], sCB[GDIR], sWt[GDIR];

    int tid = threadIdx.x;

    // ---- decode this block's 16 directions ----
    if (tid < GDIR) {
        int dir = blockIdx.x * GDIR + tid;
        int i, j;
        float cA, cB, wt;  // wt = polarization_weight * 24 (d4 = 24 * Taylor coeff)
        if (dir < 64) {                    // 4*e_i ; alpha*24 = 8.625
            i = dir; j = dir; cA = 4.f; cB = 0.f; wt = 8.625f;
        } else if (dir < 4096) {           // 3 e_i + e_j, i != j ; beta*24 = -2/3
            int p = dir - 64;
            i = p / 63;
            int r = p - i * 63;
            j = r + (r >= i ? 1 : 0);
            cA = 3.f; cB = 1.f; wt = -2.f / 3.f;
        } else {                           // 2 e_i + 2 e_j, i < j ; gamma*24 = 1.25
            int p = dir - 4096;
            int ii = 0;
            while (p >= 63 - ii) { p -= 63 - ii; ii++; }
            i = ii; j = ii + 1 + p;
            cA = 2.f; cB = 2.f; wt = 1.25f;
        }
        sI[tid] = i; sJ[tid] = j; sCA[tid] = cA; sCB[tid] = cB; sWt[tid] = wt;
    }
    if (tid < DD) sx[tid] = x[tid];
    __syncthreads();

    // ---- layer-1 forward + jet constants (thread = neuron m) ----
    int m = tid;
    float u0 = b1[m];
    {
        const float4* w1r = (const float4*)(W1 + m * DD);
#pragma unroll
        for (int d4i = 0; d4i < DD / 4; d4i++) {
            float4 wv = w1r[d4i];
            const float4 xv = *(const float4*)(sx + 4 * d4i);
            u0 += wv.x * xv.x + wv.y * xv.y + wv.z * xv.z + wv.w * xv.w;
        }
    }
    float h0 = tanhf(u0);
    float w0 = 1.f - h0 * h0;
    float c1 = w0;
    float c2 = -h0 * w0;
    float c3 = w0 * (2.f * h0 * h0 - w0) * (1.f / 3.f);
    float c4 = -h0 * w0 * (h0 * h0 - 2.f * w0) * (1.f / 3.f);
    sh0[m] = h0;

    // ---- build jet columns (W1 row m is L1-hot from the forward pass) ----
#pragma unroll
    for (int dL = 0; dL < GDIR; dL++) {
        float u1 = sCA[dL] * W1[m * DD + sI[dL]] + sCB[dL] * W1[m * DD + sJ[dL]];
        float u2 = u1 * u1;
        *(float4*)(sH + m * 64 + dL * 4) =
            make_float4(c1 * u1, c2 * u2, c3 * u2 * u1, c4 * u2 * u2);
    }
    __syncthreads();

    // ---- K-tiled GEMM: 256 n-rows x 64 cols, K=256 ----
    // thread: tn in [0,64) -> n = 4*tn+q ; tc in [0,4) -> cols 16*tc..16*tc+15
    int tn = tid & 63, tc = tid >> 6;
    unsigned long long acc[4][8];
#pragma unroll
    for (int a = 0; a < 4; a++)
#pragma unroll
        for (int b = 0; b < 8; b++) acc[a][b] = 0ull;
    float a0[4] = {0.f, 0.f, 0.f, 0.f};

    const float4* W2v = (const float4*)W2;
#pragma unroll 1
    for (int t = 0; t < H / KT; t++) {
        int m0 = t * KT;
        // stage W2T tile: coalesced row reads, transposed smem writes
#pragma unroll
        for (int k = 0; k < 8; k++) {
            int idx4 = k * 256 + tid;           // 0..2047 float4s
            int n    = idx4 >> 3;               // output row
            int mmb  = (idx4 & 7) * 4;          // m-within-tile base
            float4 v = __ldg(&W2v[n * (H / 4) + ((m0 + mmb) >> 2)]);
            sW[(mmb + 0) * SW_STRIDE + n] = v.x;
            sW[(mmb + 1) * SW_STRIDE + n] = v.y;
            sW[(mmb + 2) * SW_STRIDE + n] = v.z;
            sW[(mmb + 3) * SW_STRIDE + n] = v.w;
        }
        __syncthreads();

#pragma unroll 2
        for (int mm = 0; mm < KT; mm++) {
            int mg = m0 + mm;
            float4 w = *(const float4*)(sW + mm * SW_STRIDE + 4 * tn);
            unsigned long long wd0 = pk2(w.x, w.x), wd1 = pk2(w.y, w.y);
            unsigned long long wd2 = pk2(w.z, w.z), wd3 = pk2(w.w, w.w);
            const ulonglong2* hp = (const ulonglong2*)(sH + mg * 64 + tc * 16);
            ulonglong2 hA = hp[0], hB = hp[1], hC = hp[2], hD = hp[3];
            unsigned long long hh[8] = {hA.x, hA.y, hB.x, hB.y, hC.x, hC.y, hD.x, hD.y};
            float h0v = sh0[mg];
            a0[0] += w.x * h0v; a0[1] += w.y * h0v;
            a0[2] += w.z * h0v; a0[3] += w.w * h0v;
#pragma unroll
            for (int c = 0; c < 8; c++) {
                acc[0][c] = f2(hh[c], wd0, acc[0][c]);
                acc[1][c] = f2(hh[c], wd1, acc[1][c]);
                acc[2][c] = f2(hh[c], wd2, acc[2][c]);
                acc[3][c] = f2(hh[c], wd3, acc[3][c]);
            }
        }
        __syncthreads();
    }

    // ---- epilogue: layer-2 order-4 tanh jet, dot with W3, weight ----
    float g0v[4], om0v[4], w3v[4];
#pragma unroll
    for (int q = 0; q < 4; q++) {
        int ng = tn * 4 + q;
        float g0 = tanhf(a0[q] + b2[ng]);
        g0v[q] = g0;
        om0v[q] = 1.f - g0 * g0;
        w3v[q] = W3[ng];
    }
    float local = 0.f;
#pragma unroll
    for (int dL = 0; dL < 4; dL++) {
        float psum = 0.f;
#pragma unroll
        for (int q = 0; q < 4; q++) {
            float a1, a2, a3, a4;
            up2(acc[q][dL * 2], a1, a2);
            up2(acc[q][dL * 2 + 1], a3, a4);
            float g0 = g0v[q], om0 = om0v[q];
            float g1 = om0 * a1;
            float om1 = -2.f * g0 * g1;
            float g2 = 0.5f * a1 * om1 + a2 * om0;
            float om2 = -(2.f * g0 * g2 + g1 * g1);
            float g3 = (a1 * om2 + 2.f * a2 * om1) * (1.f / 3.f) + a3 * om0;
            float om3 = -2.f * (g0 * g3 + g1 * g2);
            float g4 = 0.25f * (a1 * om3 + 2.f * a2 * om2 + 3.f * a3 * om1) + a4 * om0;
            psum += w3v[q] * g4;
        }
        local += sWt[tc * 4 + dL] * psum;
    }

    // ---- block reduction + global accumulate ----
    __syncthreads();
    double* sred = (double*)sm;
    sred[tid] = (double)local;
    __syncthreads();
    for (int s = 128; s > 0; s >>= 1) {
        if (tid < s) sred[tid] += sred[tid + s];
        __syncthreads();
    }
    if (tid == 0) {
        atomicAdd(&g_accum, sred[0]);
        __threadfence();
        unsigned int old = atomicAdd(&g_done, 1u);
        if (old == NBLK - 1) {
            double v = atomicAdd(&g_accum, 0.0);  // fenced read of final sum
            out[0] = (float)v;
            g_accum = 0.0;    // reset for next graph replay
            g_done = 0u;
            __threadfence();
        }
    }
}

// ---------------- launch ----------------
extern "C" void kernel_launch(void* const* d_in, const int* in_sizes, int n_in,
                              void* d_out, int out_size) {
    const float* x  = (const float*)d_in[0];
    const float* W1 = (const float*)d_in[1];
    const float* b1 = (const float*)d_in[2];
    const float* W2 = (const float*)d_in[3];
    const float* b2 = (const float*)d_in[4];
    const float* W3 = (const float*)d_in[5];
    // d_in[6] = b3: does not affect the 4th derivative
    float* out = (float*)d_out;

    const int smem = (16384 + 8320 + 256 + 64) * 4;  // 100096 B
    cudaFuncSetAttribute(k_all, cudaFuncAttributeMaxDynamicSharedMemorySize, smem);
    k_all<<<NBLK, 256, smem>>>(x, W1, b1, W2, b2, W3, out);
}

// round 4
// speedup vs baseline: 2.7778x; 2.7778x over previous
#include <cuda_runtime.h>
#include <cstdint>

#define H 256
#define DD 64
#define NB_MAIN 64          // blocks in k_main (4 output neurons each)

// ---------------- persistent device state (no allocations) ----------------
__device__ float g_h1[H], g_h2[H], g_h3[H], g_h4[H], g_s[H];
__device__ float g_gd[4][H];     // g', g'', g''', g'''' at a_n
__device__ float g_G[H * H];     // Gram: G[m,m'] = sum_i W1[m,i] W1[m',i]
__device__ double g_accum = 0.0;
__device__ unsigned int g_done = 0;

// ---------------- kernel 1: setup (1 block) + Gram (64 blocks) ----------------
// Block 64: layer-1/2 forward, tanh derivative chains h'..h'''', g'..g'''',
//           row square-norms s_m.
// Blocks 0..63: Gram rows m0..m0+3 (G is symmetric; we fill all rows).
__global__ __launch_bounds__(256) void k_pre(
    const float* __restrict__ x,  const float* __restrict__ W1,
    const float* __restrict__ b1, const float* __restrict__ W2,
    const float* __restrict__ b2)
{
    int tid = threadIdx.x;
    if (blockIdx.x == NB_MAIN) {
        // ---- setup ----
        __shared__ float sx[DD];
        __shared__ float sh[H];
        if (tid < DD) sx[tid] = x[tid];
        __syncthreads();

        int m = tid;
        float z = b1[m], s = 0.f;
        const float4* wr = (const float4*)(W1 + m * DD);
#pragma unroll
        for (int i = 0; i < DD / 4; i++) {
            float4 w = wr[i];
            float4 xv = *(const float4*)(sx + 4 * i);
            z += w.x * xv.x + w.y * xv.y + w.z * xv.z + w.w * xv.w;
            s += w.x * w.x + w.y * w.y + w.z * w.z + w.w * w.w;
        }
        float h = tanhf(z), w = 1.f - h * h;
        g_h1[m] = w;                              // h'
        g_h2[m] = -2.f * h * w;                   // h''
        g_h3[m] = (4.f * h * h - 2.f * w) * w;    // h''' = -2w^2 + 4h^2 w
        g_h4[m] = (16.f * w - 8.f * h * h) * h * w; // h'''' = 16hw^2 - 8h^3 w
        g_s[m] = s;
        sh[m] = h;
        __syncthreads();

        int n = tid;
        float a = b2[n];
        const float4* w2r = (const float4*)(W2 + n * H);
#pragma unroll 8
        for (int i = 0; i < H / 4; i++) {
            float4 wv = __ldg(w2r + i);
            a += wv.x * sh[4 * i] + wv.y * sh[4 * i + 1] +
                 wv.z * sh[4 * i + 2] + wv.w * sh[4 * i + 3];
        }
        float g = tanhf(a), gw = 1.f - g * g;
        g_gd[0][n] = gw;
        g_gd[1][n] = -2.f * g * gw;
        g_gd[2][n] = (4.f * g * g - 2.f * gw) * gw;
        g_gd[3][n] = (16.f * gw - 8.f * g * g) * g * gw;
    } else {
        // ---- Gram rows m0..m0+3 ----
        __shared__ float srow[4][DD];
        int m0 = 4 * blockIdx.x;
        srow[tid >> 6][tid & 63] = W1[(m0 + (tid >> 6)) * DD + (tid & 63)];
        __syncthreads();

        int t = tid;
        const float4* myr = (const float4*)(W1 + t * DD);
        float a0 = 0.f, a1 = 0.f, a2 = 0.f, a3 = 0.f;
#pragma unroll
        for (int i = 0; i < DD / 4; i++) {
            float4 v = __ldg(myr + i);
            a0 += srow[0][4*i]*v.x + srow[0][4*i+1]*v.y + srow[0][4*i+2]*v.z + srow[0][4*i+3]*v.w;
            a1 += srow[1][4*i]*v.x + srow[1][4*i+1]*v.y + srow[1][4*i+2]*v.z + srow[1][4*i+3]*v.w;
            a2 += srow[2][4*i]*v.x + srow[2][4*i+1]*v.y + srow[2][4*i+2]*v.z + srow[2][4*i+3]*v.w;
            a3 += srow[3][4*i]*v.x + srow[3][4*i+1]*v.y + srow[3][4*i+2]*v.z + srow[3][4*i+3]*v.w;
        }
        g_G[(m0 + 0) * H + t] = a0;
        g_G[(m0 + 1) * H + t] = a1;
        g_G[(m0 + 2) * H + t] = a2;
        g_G[(m0 + 3) * H + t] = a3;
    }
}

// ---------------- kernel 2: main GEMMs + contractions + reduce ----------------
// Block b handles output neurons n0..n0+3.
//   M[n,t] = sum_m (W2[n,m] h1_m) G[m,t]
//   P[n,t] = sum_m (W2[n,m] h2_m) G[m,t]^2
// then per n:
//   Q = sum_t A[n,t] M[n,t],  R = sum_t B[n,t] M^2,  Z = sum_t B[n,t] P,
//   U = sum_t (W2 h3 s)[n,t] M[n,t],  L = sum_t B[n,t] s_t,  Y = sum_t (W2 h4 s^2)[n,t]
//   contrib = W3[n] * ( g4 Q^2 + g3 (2LQ + 4R) + g2 (L^2 + 2Z + 4U) + g1 Y )
__global__ __launch_bounds__(256) void k_main(
    const float* __restrict__ W2, const float* __restrict__ W3,
    float* __restrict__ out)
{
    __shared__ float sA[4][H];    // W2 * h1
    __shared__ float sB[4][H];    // W2 * h2
    __shared__ float sUU[4][H];   // W2 * h3 * s
    __shared__ float sred[8][24];

    int tid = threadIdx.x;
    int wid = tid >> 5, lane = tid & 31;
    int n0 = 4 * blockIdx.x;

    float pL[4], pY[4];
#pragma unroll
    for (int nn = 0; nn < 4; nn++) {
        int m = tid;
        float w2 = __ldg(&W2[(n0 + nn) * H + m]);
        float h1 = g_h1[m], h2 = g_h2[m], h3 = g_h3[m], h4 = g_h4[m], s = g_s[m];
        sA[nn][m] = w2 * h1;
        float bb = w2 * h2;
        sB[nn][m] = bb;
        sUU[nn][m] = w2 * h3 * s;
        pL[nn] = bb * s;
        pY[nn] = w2 * h4 * s * s;
    }
    __syncthreads();

    // main loop: thread t owns column t of M and P
    float Mv[4] = {0.f, 0.f, 0.f, 0.f};
    float Pv[4] = {0.f, 0.f, 0.f, 0.f};
    const float* Gcol = g_G + tid;
#pragma unroll 4
    for (int mp = 0; mp < H; mp++) {
        float gv = __ldg(Gcol + mp * H);
        float g2v = gv * gv;
#pragma unroll
        for (int nn = 0; nn < 4; nn++) {
            Mv[nn] += sA[nn][mp] * gv;
            Pv[nn] += sB[nn][mp] * g2v;
        }
    }

    // per-thread partial products (24 scalars)
    float p[24];
#pragma unroll
    for (int nn = 0; nn < 4; nn++) {
        float a = sA[nn][tid], b = sB[nn][tid], u = sUU[nn][tid], mv = Mv[nn];
        p[nn * 6 + 0] = a * mv;             // Q
        p[nn * 6 + 1] = b * mv * mv;        // R
        p[nn * 6 + 2] = b * Pv[nn];         // Z
        p[nn * 6 + 3] = u * mv;             // U
        p[nn * 6 + 4] = pL[nn];             // L
        p[nn * 6 + 5] = pY[nn];             // Y
    }

    // warp reduce 24 scalars
#pragma unroll
    for (int k = 0; k < 24; k++) {
        float v = p[k];
#pragma unroll
        for (int s = 16; s > 0; s >>= 1) v += __shfl_down_sync(0xFFFFFFFFu, v, s);
        p[k] = v;
    }
    if (lane == 0) {
#pragma unroll
        for (int k = 0; k < 24; k++) sred[wid][k] = p[k];
    }
    __syncthreads();

    if (tid == 0) {
        double dsum = 0.0;
#pragma unroll
        for (int nn = 0; nn < 4; nn++) {
            float Q = 0.f, R = 0.f, Z = 0.f, U = 0.f, L = 0.f, Y = 0.f;
#pragma unroll
            for (int w = 0; w < 8; w++) {
                Q += sred[w][nn * 6 + 0];
                R += sred[w][nn * 6 + 1];
                Z += sred[w][nn * 6 + 2];
                U += sred[w][nn * 6 + 3];
                L += sred[w][nn * 6 + 4];
                Y += sred[w][nn * 6 + 5];
            }
            int n = n0 + nn;
            float g1 = g_gd[0][n], g2 = g_gd[1][n], g3 = g_gd[2][n], g4 = g_gd[3][n];
            float val = g4 * Q * Q
                      + g3 * (2.f * L * Q + 4.f * R)
                      + g2 * (L * L + 2.f * Z + 4.f * U)
                      + g1 * Y;
            dsum += (double)(__ldg(&W3[n]) * val);
        }
        atomicAdd(&g_accum, dsum);
        __threadfence();
        unsigned int old = atomicAdd(&g_done, 1u);
        if (old == NB_MAIN - 1) {
            double r = atomicAdd(&g_accum, 0.0);
            out[0] = (float)r;
            g_accum = 0.0;
            g_done = 0u;
            __threadfence();
        }
    }
}

// ---------------- launch ----------------
extern "C" void kernel_launch(void* const* d_in, const int* in_sizes, int n_in,
                              void* d_out, int out_size) {
    const float* x  = (const float*)d_in[0];
    const float* W1 = (const float*)d_in[1];
    const float* b1 = (const float*)d_in[2];
    const float* W2 = (const float*)d_in[3];
    const float* b2 = (const float*)d_in[4];
    // d_in[5] = W3 ; d_in[6] = b3 (b3 does not affect the 4th derivative)
    const float* W3 = (const float*)d_in[5];
    float* out = (float*)d_out;

    k_pre<<<NB_MAIN + 1, 256>>>(x, W1, b1, W2, b2);
    k_main<<<NB_MAIN, 256>>>(W2, W3, out);
}

// round 5
// speedup vs baseline: 3.6885x; 1.3279x over previous
#include <cuda_runtime.h>
#include <cstdint>

#define H 256
#define DD 64
#define NB_PRE 64           // Gram blocks in k_pre (+1 setup block)
#define NB_MAIN 128         // blocks in k_main (2 output neurons each)

// ---------------- persistent device state (no allocations) ----------------
__device__ float g_h1[H], g_h2[H], g_h3[H], g_h4[H], g_s[H];
__device__ float g_gd[4][H];     // g', g'', g''', g'''' at a_n
__device__ float g_G[H * H];     // Gram: G[m,t] = sum_i W1[m,i] W1[t,i]
__device__ double g_accum = 0.0;
__device__ unsigned int g_done = 0;

// ---------------- kernel 1: setup (1 block) + Gram (64 blocks) ----------------
__global__ __launch_bounds__(256) void k_pre(
    const float* __restrict__ x,  const float* __restrict__ W1,
    const float* __restrict__ b1, const float* __restrict__ W2,
    const float* __restrict__ b2)
{
    int tid = threadIdx.x;
    if (blockIdx.x == NB_PRE) {
        // ---- forward pass + tanh derivative chains ----
        __shared__ float sx[DD];
        __shared__ float sh[H];
        if (tid < DD) sx[tid] = x[tid];
        __syncthreads();

        int m = tid;
        float z = b1[m], s = 0.f;
        const float4* wr = (const float4*)(W1 + m * DD);
#pragma unroll
        for (int i = 0; i < DD / 4; i++) {
            float4 w = wr[i];
            float4 xv = *(const float4*)(sx + 4 * i);
            z += w.x * xv.x + w.y * xv.y + w.z * xv.z + w.w * xv.w;
            s += w.x * w.x + w.y * w.y + w.z * w.z + w.w * w.w;
        }
        float h = tanhf(z), w = 1.f - h * h;
        g_h1[m] = w;
        g_h2[m] = -2.f * h * w;
        g_h3[m] = (4.f * h * h - 2.f * w) * w;
        g_h4[m] = (16.f * w - 8.f * h * h) * h * w;
        g_s[m] = s;
        sh[m] = h;
        __syncthreads();

        int n = tid;
        float a = b2[n];
        const float4* w2r = (const float4*)(W2 + n * H);
#pragma unroll 8
        for (int i = 0; i < H / 4; i++) {
            float4 wv = __ldg(w2r + i);
            a += wv.x * sh[4 * i] + wv.y * sh[4 * i + 1] +
                 wv.z * sh[4 * i + 2] + wv.w * sh[4 * i + 3];
        }
        float g = tanhf(a), gw = 1.f - g * g;
        g_gd[0][n] = gw;
        g_gd[1][n] = -2.f * g * gw;
        g_gd[2][n] = (4.f * g * g - 2.f * gw) * gw;
        g_gd[3][n] = (16.f * gw - 8.f * g * g) * g * gw;
    } else {
        // ---- Gram rows m0..m0+3 ----
        __shared__ float srow[4][DD];
        int m0 = 4 * blockIdx.x;
        srow[tid >> 6][tid & 63] = W1[(m0 + (tid >> 6)) * DD + (tid & 63)];
        __syncthreads();

        int t = tid;
        const float4* myr = (const float4*)(W1 + t * DD);
        float a0 = 0.f, a1 = 0.f, a2 = 0.f, a3 = 0.f;
#pragma unroll
        for (int i = 0; i < DD / 4; i++) {
            float4 v = __ldg(myr + i);
            a0 += srow[0][4*i]*v.x + srow[0][4*i+1]*v.y + srow[0][4*i+2]*v.z + srow[0][4*i+3]*v.w;
            a1 += srow[1][4*i]*v.x + srow[1][4*i+1]*v.y + srow[1][4*i+2]*v.z + srow[1][4*i+3]*v.w;
            a2 += srow[2][4*i]*v.x + srow[2][4*i+1]*v.y + srow[2][4*i+2]*v.z + srow[2][4*i+3]*v.w;
            a3 += srow[3][4*i]*v.x + srow[3][4*i+1]*v.y + srow[3][4*i+2]*v.z + srow[3][4*i+3]*v.w;
        }
        g_G[(m0 + 0) * H + t] = a0;
        g_G[(m0 + 1) * H + t] = a1;
        g_G[(m0 + 2) * H + t] = a2;
        g_G[(m0 + 3) * H + t] = a3;
    }
}

// ---------------- kernel 2: contractions (2 output neurons per block) ----------------
//   M[n,t] = sum_m (W2[n,m] h1_m) G[m,t]
//   P[n,t] = sum_m (W2[n,m] h2_m) G[m,t]^2
//   Q = <A,M>, R = <B,M^2>, Z = <B,P>, U = <W2 h3 s, M>, L = <B,s>, Y = <W2 h4 s^2, 1>
//   contrib_n = W3[n] * ( g4 Q^2 + g3 (2LQ + 4R) + g2 (L^2 + 2Z + 4U) + g1 Y )
__global__ __launch_bounds__(256) void k_main(
    const float* __restrict__ W2, const float* __restrict__ W3,
    float* __restrict__ out)
{
    __shared__ float4 sAB[H];      // {A(n0), A(n1), B(n0), B(n1)} per m
    __shared__ float sU0[H], sU1[H];
    __shared__ float sred[8][12];

    int tid = threadIdx.x;
    int wid = tid >> 5, lane = tid & 31;
    int n0 = 2 * blockIdx.x;

    float pL0, pL1, pY0, pY1;
    {
        int m = tid;
        float w20 = __ldg(&W2[n0 * H + m]);
        float w21 = __ldg(&W2[(n0 + 1) * H + m]);
        float h1 = g_h1[m], h2 = g_h2[m], h3 = g_h3[m], h4 = g_h4[m], s = g_s[m];
        float A0 = w20 * h1, A1 = w21 * h1;
        float B0 = w20 * h2, B1 = w21 * h2;
        sAB[m] = make_float4(A0, A1, B0, B1);
        sU0[m] = w20 * h3 * s;
        sU1[m] = w21 * h3 * s;
        pL0 = B0 * s;  pL1 = B1 * s;
        pY0 = w20 * h4 * s * s;
        pY1 = w21 * h4 * s * s;
    }
    __syncthreads();

    // main loop: thread t owns column t; manual 8-wide load batching for MLP
    float M0 = 0.f, M1 = 0.f, P0 = 0.f, P1 = 0.f;
    const float* Gcol = g_G + tid;
#pragma unroll 1
    for (int b = 0; b < H / 8; b++) {
        float gv[8];
#pragma unroll
        for (int u = 0; u < 8; u++) gv[u] = __ldg(Gcol + (8 * b + u) * H);
#pragma unroll
        for (int u = 0; u < 8; u++) {
            float4 ab = sAB[8 * b + u];
            float g2 = gv[u] * gv[u];
            M0 += ab.x * gv[u];
            M1 += ab.y * gv[u];
            P0 += ab.z * g2;
            P1 += ab.w * g2;
        }
    }

    // per-thread partials (12 scalars: 2 n x {Q,R,Z,U,L,Y})
    float4 ab = sAB[tid];
    float p[12];
    p[0]  = ab.x * M0;        p[1]  = ab.z * M0 * M0;  p[2]  = ab.z * P0;
    p[3]  = sU0[tid] * M0;    p[4]  = pL0;             p[5]  = pY0;
    p[6]  = ab.y * M1;        p[7]  = ab.w * M1 * M1;  p[8]  = ab.w * P1;
    p[9]  = sU1[tid] * M1;    p[10] = pL1;             p[11] = pY1;

#pragma unroll
    for (int k = 0; k < 12; k++) {
        float v = p[k];
#pragma unroll
        for (int s = 16; s > 0; s >>= 1) v += __shfl_down_sync(0xFFFFFFFFu, v, s);
        p[k] = v;
    }
    if (lane == 0) {
#pragma unroll
        for (int k = 0; k < 12; k++) sred[wid][k] = p[k];
    }
    __syncthreads();

    if (tid == 0) {
        double dsum = 0.0;
#pragma unroll
        for (int nn = 0; nn < 2; nn++) {
            float Q = 0.f, R = 0.f, Z = 0.f, U = 0.f, L = 0.f, Y = 0.f;
#pragma unroll
            for (int w = 0; w < 8; w++) {
                Q += sred[w][nn * 6 + 0];
                R += sred[w][nn * 6 + 1];
                Z += sred[w][nn * 6 + 2];
                U += sred[w][nn * 6 + 3];
                L += sred[w][nn * 6 + 4];
                Y += sred[w][nn * 6 + 5];
            }
            int n = n0 + nn;
            float g1 = g_gd[0][n], g2 = g_gd[1][n], g3 = g_gd[2][n], g4 = g_gd[3][n];
            float val = g4 * Q * Q
                      + g3 * (2.f * L * Q + 4.f * R)
                      + g2 * (L * L + 2.f * Z + 4.f * U)
                      + g1 * Y;
            dsum += (double)(__ldg(&W3[n]) * val);
        }
        atomicAdd(&g_accum, dsum);
        __threadfence();
        unsigned int old = atomicAdd(&g_done, 1u);
        if (old == NB_MAIN - 1) {
            double r = atomicAdd(&g_accum, 0.0);
            out[0] = (float)r;
            g_accum = 0.0;
            g_done = 0u;
            __threadfence();
        }
    }
}

// ---------------- launch ----------------
extern "C" void kernel_launch(void* const* d_in, const int* in_sizes, int n_in,
                              void* d_out, int out_size) {
    const float* x  = (const float*)d_in[0];
    const float* W1 = (const float*)d_in[1];
    const float* b1 = (const float*)d_in[2];
    const float* W2 = (const float*)d_in[3];
    const float* b2 = (const float*)d_in[4];
    const float* W3 = (const float*)d_in[5];
    // d_in[6] = b3: does not affect the 4th derivative
    float* out = (float*)d_out;

    k_pre<<<NB_PRE + 1, 256>>>(x, W1, b1, W2, b2);
    k_main<<<NB_MAIN, 256>>>(W2, W3, out);
}